// round 12
// baseline (speedup 1.0000x reference)
#include <cuda_runtime.h>

// ---------------------------------------------------------------------------
// DyNet2D R11: Winograd F(4x4,3x3). R9 config (256 thr, 2 CTA/SM, T=2,
// streaming phase B) + phase-C q-loop unroll bounded to 3 so operand batching
// (3x12=36 regs) + 72 accs fits under the 128-reg cap -> no spills.
// ---------------------------------------------------------------------------

#define HW (512 * 512)

__device__ float g_partial[1024];                       // (b*16+c)*4 + quarter
__device__ __align__(16) float g_u[16 * 16 * 9 * 64];   // [b][ic][q][oc][4]

// ------------------------------ 1) pooling --------------------------------
__global__ void pool_kernel(const float* __restrict__ x) {
    const int blk = blockIdx.x;
    const int bc  = blk >> 2;
    const int q   = blk & 3;
    const float4* p = reinterpret_cast<const float4*>(x + (size_t)bc * HW + (size_t)q * 65536);
    float s = 0.0f;
    #pragma unroll 4
    for (int i = threadIdx.x; i < 16384; i += 256) {
        float4 v = p[i];
        s += (v.x + v.y) + (v.z + v.w);
    }
    #pragma unroll
    for (int o = 16; o > 0; o >>= 1) s += __shfl_down_sync(0xffffffffu, s, o);
    __shared__ float ws[8];
    if ((threadIdx.x & 31) == 0) ws[threadIdx.x >> 5] = s;
    __syncthreads();
    if (threadIdx.x == 0) {
        float t = 0.0f;
        #pragma unroll
        for (int i = 0; i < 8; i++) t += ws[i];
        g_partial[blk] = t;
    }
}

// --------------- 2) routing softmax + Winograd weight transform -----------
__global__ void mix_kernel(const float* __restrict__ w_experts,
                           const float* __restrict__ fc_w,
                           const float* __restrict__ fc_b) {
    __shared__ float pooled_s[256];
    __shared__ float r_s[16][3];
    const int tid = threadIdx.x;

    pooled_s[tid] = (g_partial[tid * 4 + 0] + g_partial[tid * 4 + 1] +
                     g_partial[tid * 4 + 2] + g_partial[tid * 4 + 3]) * (1.0f / (float)HW);
    __syncthreads();

    if (tid < 16) {
        float lg[3];
        #pragma unroll
        for (int e = 0; e < 3; e++) {
            float a = fc_b[e];
            #pragma unroll
            for (int c = 0; c < 16; c++) a += pooled_s[tid * 16 + c] * fc_w[e * 16 + c];
            lg[e] = a;
        }
        float m = fmaxf(lg[0], fmaxf(lg[1], lg[2]));
        float ex0 = expf(lg[0] - m), ex1 = expf(lg[1] - m), ex2 = expf(lg[2] - m);
        float inv = 1.0f / (ex0 + ex1 + ex2);
        r_s[tid][0] = ex0 * inv;
        r_s[tid][1] = ex1 * inv;
        r_s[tid][2] = ex2 * inv;
    }
    __syncthreads();

    for (int job = tid; job < 4096; job += 256) {
        int b  = job >> 8;
        int ic = (job >> 4) & 15;
        int oc = job & 15;

        float w[3][3];
        #pragma unroll
        for (int r = 0; r < 3; r++)
            #pragma unroll
            for (int c = 0; c < 3; c++) {
                float v = 0.0f;
                #pragma unroll
                for (int e = 0; e < 3; e++)
                    v += r_s[b][e] * w_experts[((e * 16 + oc) * 16 + ic) * 9 + r * 3 + c];
                w[r][c] = v;
            }

        float T[6][3];
        #pragma unroll
        for (int c = 0; c < 3; c++) {
            float w0 = w[0][c], w1 = w[1][c], w2 = w[2][c];
            T[0][c] = 0.25f * w0;
            T[1][c] = (-1.0f / 6.0f) * (w0 + w1 + w2);
            T[2][c] = (1.0f / 6.0f) * (-w0 + w1 - w2);
            T[3][c] = (1.0f / 24.0f) * w0 + (1.0f / 12.0f) * w1 + (1.0f / 6.0f) * w2;
            T[4][c] = (1.0f / 24.0f) * w0 - (1.0f / 12.0f) * w1 + (1.0f / 6.0f) * w2;
            T[5][c] = w2;
        }
        float u36[36];
        #pragma unroll
        for (int i = 0; i < 6; i++) {
            float t0 = T[i][0], t1 = T[i][1], t2 = T[i][2];
            u36[i * 6 + 0] = 0.25f * t0;
            u36[i * 6 + 1] = (-1.0f / 6.0f) * (t0 + t1 + t2);
            u36[i * 6 + 2] = (1.0f / 6.0f) * (-t0 + t1 - t2);
            u36[i * 6 + 3] = (1.0f / 24.0f) * t0 + (1.0f / 12.0f) * t1 + (1.0f / 6.0f) * t2;
            u36[i * 6 + 4] = (1.0f / 24.0f) * t0 - (1.0f / 12.0f) * t1 + (1.0f / 6.0f) * t2;
            u36[i * 6 + 5] = t2;
        }
        float* base = g_u + (size_t)(b * 16 + ic) * 576 + oc * 4;
        #pragma unroll
        for (int q = 0; q < 9; q++) {
            base[q * 64 + 0] = u36[q * 4 + 0];
            base[q * 64 + 1] = u36[q * 4 + 1];
            base[q * 64 + 2] = u36[q * 4 + 2];
            base[q * 64 + 3] = u36[q * 4 + 3];
        }
    }
}

// ------- no-op: shifts ncu's -s 5 capture slot onto conv_kernel -----------
__global__ void tag_kernel() {}

// ------------------------- 3) Winograd conv -------------------------------
__device__ __forceinline__ void btrans(float v0, float v1, float v2, float v3,
                                       float v4, float v5,
                                       float& o0, float& o1, float& o2,
                                       float& o3, float& o4, float& o5) {
    float a = v1 + v2;
    float b = v3 + v4;
    float c = v1 - v2;
    float e = v4 - v3;
    float f = v3 - v1;
    float g = v4 - v2;
    o0 = fmaf(4.0f, v0, fmaf(-5.0f, v2, v4));
    o1 = fmaf(-4.0f, a, b);
    o2 = fmaf(4.0f, c, e);
    o3 = fmaf(2.0f, f, g);
    o4 = fmaf(-2.0f, f, g);
    o5 = fmaf(4.0f, v1, fmaf(-5.0f, v3, v5));
}

__device__ __forceinline__ void atrans(float v0, float v1, float v2, float v3,
                                       float v4, float v5,
                                       float& o0, float& o1, float& o2, float& o3) {
    float s1 = v1 + v2;
    float s2 = v1 - v2;
    float s3 = v3 + v4;
    float s4 = v3 - v4;
    o0 = v0 + s1 + s3;
    o1 = fmaf(2.0f, s4, s2);
    o2 = fmaf(4.0f, s3, s1);
    o3 = fmaf(8.0f, s4, s2) + v5;
}

// SMEM (floats):
//   bd_s  : [16 ic][32 tile][36] -> 18432  (offset 0)
//   union : 10368                 (offset 18432)
//       phases A/B: in_s [16 ic][18 rows][36 stride] (cols 0..33 used)
//       phase  C  : w_s  [16 ic][9 q][16 oc][4] = 9216
// total 28800 floats = 115200 bytes -> 2 CTAs/SM
__global__ void __launch_bounds__(256, 2)
conv_kernel(const float* __restrict__ x, const float* __restrict__ bias,
            float* __restrict__ out) {
    extern __shared__ float smem[];
    float* bd_s = smem;
    float* un_s = smem + 18432;      // in_s during A/B, w_s during C

    const int tid = threadIdx.x;
    const int b   = blockIdx.z;
    const int x0  = blockIdx.x * 32;
    const int y0  = blockIdx.y * 16;

    const int oc  = tid & 15;
    const int grp = tid >> 4;        // 0..15 -> tiles 2*grp, 2*grp+1

    const float bv = bias[oc];
    const float* xb = x + (size_t)b * 16 * HW;

    // ---- phase A: input tile 16ic x 18 x 34 (reflect halo), stride 36 ----
    for (int i = tid; i < 9792; i += 256) {
        int c   = i / 612;                   // 18*34
        int rem = i - c * 612;
        int row = rem / 34;
        int col = rem - row * 34;
        int gy = y0 + row - 1; gy = gy < 0 ? -gy : (gy > 511 ? 1022 - gy : gy);
        int gx = x0 + col - 1; gx = gx < 0 ? -gx : (gx > 511 ? 1022 - gx : gx);
        un_s[c * 648 + row * 36 + col] = xb[(c << 18) + (gy << 9) + gx];
    }
    __syncthreads();

    // ---- phase B: streaming input transform, 2 jobs/thread ----
    #pragma unroll 1
    for (int s = 0; s < 2; s++) {
        const int job  = tid + s * 256;
        const int b_ic = job >> 5;
        const int b_t  = job & 31;
        const int b_tx = b_t & 7;
        const int b_ty = b_t >> 3;
        const float* p = un_s + b_ic * 648 + (4 * b_ty) * 36 + 4 * b_tx;

        float t[6][6];
        #pragma unroll
        for (int c = 0; c < 6; c++) {
            float d0 = p[0 * 36 + c];
            float d1 = p[1 * 36 + c];
            float d2 = p[2 * 36 + c];
            float d3 = p[3 * 36 + c];
            float d4 = p[4 * 36 + c];
            float d5 = p[5 * 36 + c];
            btrans(d0, d1, d2, d3, d4, d5,
                   t[0][c], t[1][c], t[2][c], t[3][c], t[4][c], t[5][c]);
        }
        float* dst = bd_s + (b_ic * 32 + b_t) * 36;
        #pragma unroll
        for (int i = 0; i < 6; i++) {
            float o0, o1, o2, o3, o4, o5;
            btrans(t[i][0], t[i][1], t[i][2], t[i][3], t[i][4], t[i][5],
                   o0, o1, o2, o3, o4, o5);
            dst[i * 6 + 0] = o0;
            dst[i * 6 + 1] = o1;
            dst[i * 6 + 2] = o2;
            dst[i * 6 + 3] = o3;
            dst[i * 6 + 4] = o4;
            dst[i * 6 + 5] = o5;
        }
    }
    __syncthreads();

    // ---- load transformed weights into union (in_s dead now) ----
    {
        const float4* src = reinterpret_cast<const float4*>(g_u + (size_t)b * 9216);
        float4* dst = reinterpret_cast<float4*>(un_s);
        #pragma unroll
        for (int k = 0; k < 9; k++) {
            int i = tid + k * 256;
            if (i < 2304) dst[i] = src[i];
        }
    }
    __syncthreads();

    // ---- phase C: accumulate m[2][36] over 16 ic ----
    // q-loop unroll bounded to 3: operand batch 3*(u+b0+b1)=36 regs, keeping
    // total (72 accs + 36 + misc) under the 128-reg cap -> no spills.
    float m0[36], m1[36];
    #pragma unroll
    for (int j = 0; j < 36; j++) { m0[j] = 0.0f; m1[j] = 0.0f; }
    {
        const float* bdp0 = bd_s + (grp * 2 + 0) * 36;
        const float* bdp1 = bd_s + (grp * 2 + 1) * 36;
        const float* wq   = un_s + oc * 4;
        #pragma unroll 1
        for (int ic = 0; ic < 16; ic++) {
            #pragma unroll 3
            for (int q = 0; q < 9; q++) {
                float4 u  = *reinterpret_cast<const float4*>(wq + q * 64);
                float4 b0 = *reinterpret_cast<const float4*>(bdp0 + q * 4);
                float4 b1 = *reinterpret_cast<const float4*>(bdp1 + q * 4);
                m0[q*4+0] = fmaf(b0.x, u.x, m0[q*4+0]);
                m0[q*4+1] = fmaf(b0.y, u.y, m0[q*4+1]);
                m0[q*4+2] = fmaf(b0.z, u.z, m0[q*4+2]);
                m0[q*4+3] = fmaf(b0.w, u.w, m0[q*4+3]);
                m1[q*4+0] = fmaf(b1.x, u.x, m1[q*4+0]);
                m1[q*4+1] = fmaf(b1.y, u.y, m1[q*4+1]);
                m1[q*4+2] = fmaf(b1.z, u.z, m1[q*4+2]);
                m1[q*4+3] = fmaf(b1.w, u.w, m1[q*4+3]);
            }
            bdp0 += 32 * 36;
            bdp1 += 32 * 36;
            wq   += 576;
        }
    }

    // ---- phase D: A^T m A + bias for both tiles ----
    #pragma unroll
    for (int t2 = 0; t2 < 2; t2++) {
        const float* m = t2 ? m1 : m0;
        const int tile = grp * 2 + t2;
        const int tx = tile & 7;
        const int ty = tile >> 3;

        float t[4][6];
        #pragma unroll
        for (int j = 0; j < 6; j++)
            atrans(m[0 * 6 + j], m[1 * 6 + j], m[2 * 6 + j],
                   m[3 * 6 + j], m[4 * 6 + j], m[5 * 6 + j],
                   t[0][j], t[1][j], t[2][j], t[3][j]);

        float* op = out + ((size_t)(b * 16 + oc) << 18) +
                    ((size_t)(y0 + 4 * ty) << 9) + (x0 + 4 * tx);
        #pragma unroll
        for (int r = 0; r < 4; r++) {
            float o0, o1, o2, o3;
            atrans(t[r][0], t[r][1], t[r][2], t[r][3], t[r][4], t[r][5],
                   o0, o1, o2, o3);
            *reinterpret_cast<float4*>(op + ((size_t)r << 9)) =
                make_float4(o0 + bv, o1 + bv, o2 + bv, o3 + bv);
        }
    }
}

// ---------------------------------------------------------------------------
extern "C" void kernel_launch(void* const* d_in, const int* in_sizes, int n_in,
                              void* d_out, int out_size) {
    const float* x         = (const float*)d_in[0];
    const float* w_experts = (const float*)d_in[1];
    const float* bias      = (const float*)d_in[2];
    const float* fc_w      = (const float*)d_in[3];
    const float* fc_b      = (const float*)d_in[4];
    float* out = (float*)d_out;

    const int smem_bytes = 28800 * 4;   // 115200
    cudaFuncSetAttribute(conv_kernel, cudaFuncAttributeMaxDynamicSharedMemorySize, smem_bytes);

    pool_kernel<<<1024, 256>>>(x);
    mix_kernel<<<1, 256>>>(w_experts, fc_w, fc_b);
    tag_kernel<<<1, 32>>>();
    conv_kernel<<<dim3(16, 32, 16), 256, smem_bytes>>>(x, bias, out);
}

// round 13
// speedup vs baseline: 1.7850x; 1.7850x over previous
#include <cuda_runtime.h>

// ---------------------------------------------------------------------------
// DyNet2D R12: Winograd F(4x4,3x3). R9 config (256 thr, 2 CTA/SM, T=2,
// streaming phase B) with phase-C loop INTERCHANGE: q fully unrolled outer
// (static accumulator indices -> stays in registers), ic inner with small
// scalar accumulator set (8 regs) -> no spills, no local-memory demotion.
// ---------------------------------------------------------------------------

#define HW (512 * 512)

__device__ float g_partial[1024];                       // (b*16+c)*4 + quarter
__device__ __align__(16) float g_u[16 * 16 * 9 * 64];   // [b][ic][q][oc][4]

// ------------------------------ 1) pooling --------------------------------
__global__ void pool_kernel(const float* __restrict__ x) {
    const int blk = blockIdx.x;
    const int bc  = blk >> 2;
    const int q   = blk & 3;
    const float4* p = reinterpret_cast<const float4*>(x + (size_t)bc * HW + (size_t)q * 65536);
    float s = 0.0f;
    #pragma unroll 4
    for (int i = threadIdx.x; i < 16384; i += 256) {
        float4 v = p[i];
        s += (v.x + v.y) + (v.z + v.w);
    }
    #pragma unroll
    for (int o = 16; o > 0; o >>= 1) s += __shfl_down_sync(0xffffffffu, s, o);
    __shared__ float ws[8];
    if ((threadIdx.x & 31) == 0) ws[threadIdx.x >> 5] = s;
    __syncthreads();
    if (threadIdx.x == 0) {
        float t = 0.0f;
        #pragma unroll
        for (int i = 0; i < 8; i++) t += ws[i];
        g_partial[blk] = t;
    }
}

// --------------- 2) routing softmax + Winograd weight transform -----------
__global__ void mix_kernel(const float* __restrict__ w_experts,
                           const float* __restrict__ fc_w,
                           const float* __restrict__ fc_b) {
    __shared__ float pooled_s[256];
    __shared__ float r_s[16][3];
    const int tid = threadIdx.x;

    pooled_s[tid] = (g_partial[tid * 4 + 0] + g_partial[tid * 4 + 1] +
                     g_partial[tid * 4 + 2] + g_partial[tid * 4 + 3]) * (1.0f / (float)HW);
    __syncthreads();

    if (tid < 16) {
        float lg[3];
        #pragma unroll
        for (int e = 0; e < 3; e++) {
            float a = fc_b[e];
            #pragma unroll
            for (int c = 0; c < 16; c++) a += pooled_s[tid * 16 + c] * fc_w[e * 16 + c];
            lg[e] = a;
        }
        float m = fmaxf(lg[0], fmaxf(lg[1], lg[2]));
        float ex0 = expf(lg[0] - m), ex1 = expf(lg[1] - m), ex2 = expf(lg[2] - m);
        float inv = 1.0f / (ex0 + ex1 + ex2);
        r_s[tid][0] = ex0 * inv;
        r_s[tid][1] = ex1 * inv;
        r_s[tid][2] = ex2 * inv;
    }
    __syncthreads();

    for (int job = tid; job < 4096; job += 256) {
        int b  = job >> 8;
        int ic = (job >> 4) & 15;
        int oc = job & 15;

        float w[3][3];
        #pragma unroll
        for (int r = 0; r < 3; r++)
            #pragma unroll
            for (int c = 0; c < 3; c++) {
                float v = 0.0f;
                #pragma unroll
                for (int e = 0; e < 3; e++)
                    v += r_s[b][e] * w_experts[((e * 16 + oc) * 16 + ic) * 9 + r * 3 + c];
                w[r][c] = v;
            }

        float T[6][3];
        #pragma unroll
        for (int c = 0; c < 3; c++) {
            float w0 = w[0][c], w1 = w[1][c], w2 = w[2][c];
            T[0][c] = 0.25f * w0;
            T[1][c] = (-1.0f / 6.0f) * (w0 + w1 + w2);
            T[2][c] = (1.0f / 6.0f) * (-w0 + w1 - w2);
            T[3][c] = (1.0f / 24.0f) * w0 + (1.0f / 12.0f) * w1 + (1.0f / 6.0f) * w2;
            T[4][c] = (1.0f / 24.0f) * w0 - (1.0f / 12.0f) * w1 + (1.0f / 6.0f) * w2;
            T[5][c] = w2;
        }
        float u36[36];
        #pragma unroll
        for (int i = 0; i < 6; i++) {
            float t0 = T[i][0], t1 = T[i][1], t2 = T[i][2];
            u36[i * 6 + 0] = 0.25f * t0;
            u36[i * 6 + 1] = (-1.0f / 6.0f) * (t0 + t1 + t2);
            u36[i * 6 + 2] = (1.0f / 6.0f) * (-t0 + t1 - t2);
            u36[i * 6 + 3] = (1.0f / 24.0f) * t0 + (1.0f / 12.0f) * t1 + (1.0f / 6.0f) * t2;
            u36[i * 6 + 4] = (1.0f / 24.0f) * t0 - (1.0f / 12.0f) * t1 + (1.0f / 6.0f) * t2;
            u36[i * 6 + 5] = t2;
        }
        float* base = g_u + (size_t)(b * 16 + ic) * 576 + oc * 4;
        #pragma unroll
        for (int q = 0; q < 9; q++) {
            base[q * 64 + 0] = u36[q * 4 + 0];
            base[q * 64 + 1] = u36[q * 4 + 1];
            base[q * 64 + 2] = u36[q * 4 + 2];
            base[q * 64 + 3] = u36[q * 4 + 3];
        }
    }
}

// ------- no-op: shifts ncu's -s 5 capture slot onto conv_kernel -----------
__global__ void tag_kernel() {}

// ------------------------- 3) Winograd conv -------------------------------
__device__ __forceinline__ void btrans(float v0, float v1, float v2, float v3,
                                       float v4, float v5,
                                       float& o0, float& o1, float& o2,
                                       float& o3, float& o4, float& o5) {
    float a = v1 + v2;
    float b = v3 + v4;
    float c = v1 - v2;
    float e = v4 - v3;
    float f = v3 - v1;
    float g = v4 - v2;
    o0 = fmaf(4.0f, v0, fmaf(-5.0f, v2, v4));
    o1 = fmaf(-4.0f, a, b);
    o2 = fmaf(4.0f, c, e);
    o3 = fmaf(2.0f, f, g);
    o4 = fmaf(-2.0f, f, g);
    o5 = fmaf(4.0f, v1, fmaf(-5.0f, v3, v5));
}

__device__ __forceinline__ void atrans(float v0, float v1, float v2, float v3,
                                       float v4, float v5,
                                       float& o0, float& o1, float& o2, float& o3) {
    float s1 = v1 + v2;
    float s2 = v1 - v2;
    float s3 = v3 + v4;
    float s4 = v3 - v4;
    o0 = v0 + s1 + s3;
    o1 = fmaf(2.0f, s4, s2);
    o2 = fmaf(4.0f, s3, s1);
    o3 = fmaf(8.0f, s4, s2) + v5;
}

// SMEM (floats):
//   bd_s  : [16 ic][32 tile][36] -> 18432  (offset 0)
//   union : 10368                 (offset 18432)
//       phases A/B: in_s [16 ic][18 rows][36 stride] (cols 0..33 used)
//       phase  C  : w_s  [16 ic][9 q][16 oc][4] = 9216
// total 28800 floats = 115200 bytes -> 2 CTAs/SM
__global__ void __launch_bounds__(256, 2)
conv_kernel(const float* __restrict__ x, const float* __restrict__ bias,
            float* __restrict__ out) {
    extern __shared__ float smem[];
    float* bd_s = smem;
    float* un_s = smem + 18432;      // in_s during A/B, w_s during C

    const int tid = threadIdx.x;
    const int b   = blockIdx.z;
    const int x0  = blockIdx.x * 32;
    const int y0  = blockIdx.y * 16;

    const int oc  = tid & 15;
    const int grp = tid >> 4;        // 0..15 -> tiles 2*grp, 2*grp+1

    const float bv = bias[oc];
    const float* xb = x + (size_t)b * 16 * HW;

    // ---- phase A: input tile 16ic x 18 x 34 (reflect halo), stride 36 ----
    for (int i = tid; i < 9792; i += 256) {
        int c   = i / 612;                   // 18*34
        int rem = i - c * 612;
        int row = rem / 34;
        int col = rem - row * 34;
        int gy = y0 + row - 1; gy = gy < 0 ? -gy : (gy > 511 ? 1022 - gy : gy);
        int gx = x0 + col - 1; gx = gx < 0 ? -gx : (gx > 511 ? 1022 - gx : gx);
        un_s[c * 648 + row * 36 + col] = xb[(c << 18) + (gy << 9) + gx];
    }
    __syncthreads();

    // ---- phase B: streaming input transform, 2 jobs/thread ----
    #pragma unroll 1
    for (int s = 0; s < 2; s++) {
        const int job  = tid + s * 256;
        const int b_ic = job >> 5;
        const int b_t  = job & 31;
        const int b_tx = b_t & 7;
        const int b_ty = b_t >> 3;
        const float* p = un_s + b_ic * 648 + (4 * b_ty) * 36 + 4 * b_tx;

        float t[6][6];
        #pragma unroll
        for (int c = 0; c < 6; c++) {
            float d0 = p[0 * 36 + c];
            float d1 = p[1 * 36 + c];
            float d2 = p[2 * 36 + c];
            float d3 = p[3 * 36 + c];
            float d4 = p[4 * 36 + c];
            float d5 = p[5 * 36 + c];
            btrans(d0, d1, d2, d3, d4, d5,
                   t[0][c], t[1][c], t[2][c], t[3][c], t[4][c], t[5][c]);
        }
        float* dst = bd_s + (b_ic * 32 + b_t) * 36;
        #pragma unroll
        for (int i = 0; i < 6; i++) {
            float o0, o1, o2, o3, o4, o5;
            btrans(t[i][0], t[i][1], t[i][2], t[i][3], t[i][4], t[i][5],
                   o0, o1, o2, o3, o4, o5);
            dst[i * 6 + 0] = o0;
            dst[i * 6 + 1] = o1;
            dst[i * 6 + 2] = o2;
            dst[i * 6 + 3] = o3;
            dst[i * 6 + 4] = o4;
            dst[i * 6 + 5] = o5;
        }
    }
    __syncthreads();

    // ---- load transformed weights into union (in_s dead now) ----
    {
        const float4* src = reinterpret_cast<const float4*>(g_u + (size_t)b * 9216);
        float4* dst = reinterpret_cast<float4*>(un_s);
        #pragma unroll
        for (int k = 0; k < 9; k++) {
            int i = tid + k * 256;
            if (i < 2304) dst[i] = src[i];
        }
    }
    __syncthreads();

    // ---- phase C: q fully-unrolled OUTER, ic inner ----
    // Per q block: 8 scalar accumulators over 16 ic, then commit to m with
    // static indices. Peak live ~ 72 m + 8 acc + operands -> fits 128 regs.
    float m0[36], m1[36];
    {
        const float* wq   = un_s + oc * 4;                 // + ic*576 + q*64
        const float* bdp0 = bd_s + (grp * 2 + 0) * 36;     // + ic*1152 + q*4
        const float* bdp1 = bd_s + (grp * 2 + 1) * 36;
        #pragma unroll
        for (int q = 0; q < 9; q++) {
            float a00 = 0.f, a01 = 0.f, a02 = 0.f, a03 = 0.f;
            float a10 = 0.f, a11 = 0.f, a12 = 0.f, a13 = 0.f;
            #pragma unroll 2
            for (int ic = 0; ic < 16; ic++) {
                float4 u  = *reinterpret_cast<const float4*>(wq   + ic * 576  + q * 64);
                float4 b0 = *reinterpret_cast<const float4*>(bdp0 + ic * 1152 + q * 4);
                float4 b1 = *reinterpret_cast<const float4*>(bdp1 + ic * 1152 + q * 4);
                a00 = fmaf(b0.x, u.x, a00);
                a01 = fmaf(b0.y, u.y, a01);
                a02 = fmaf(b0.z, u.z, a02);
                a03 = fmaf(b0.w, u.w, a03);
                a10 = fmaf(b1.x, u.x, a10);
                a11 = fmaf(b1.y, u.y, a11);
                a12 = fmaf(b1.z, u.z, a12);
                a13 = fmaf(b1.w, u.w, a13);
            }
            m0[q * 4 + 0] = a00; m0[q * 4 + 1] = a01;
            m0[q * 4 + 2] = a02; m0[q * 4 + 3] = a03;
            m1[q * 4 + 0] = a10; m1[q * 4 + 1] = a11;
            m1[q * 4 + 2] = a12; m1[q * 4 + 3] = a13;
        }
    }

    // ---- phase D: A^T m A + bias for both tiles ----
    #pragma unroll
    for (int t2 = 0; t2 < 2; t2++) {
        const float* m = t2 ? m1 : m0;
        const int tile = grp * 2 + t2;
        const int tx = tile & 7;
        const int ty = tile >> 3;

        float t[4][6];
        #pragma unroll
        for (int j = 0; j < 6; j++)
            atrans(m[0 * 6 + j], m[1 * 6 + j], m[2 * 6 + j],
                   m[3 * 6 + j], m[4 * 6 + j], m[5 * 6 + j],
                   t[0][j], t[1][j], t[2][j], t[3][j]);

        float* op = out + ((size_t)(b * 16 + oc) << 18) +
                    ((size_t)(y0 + 4 * ty) << 9) + (x0 + 4 * tx);
        #pragma unroll
        for (int r = 0; r < 4; r++) {
            float o0, o1, o2, o3;
            atrans(t[r][0], t[r][1], t[r][2], t[r][3], t[r][4], t[r][5],
                   o0, o1, o2, o3);
            *reinterpret_cast<float4*>(op + ((size_t)r << 9)) =
                make_float4(o0 + bv, o1 + bv, o2 + bv, o3 + bv);
        }
    }
}

// ---------------------------------------------------------------------------
extern "C" void kernel_launch(void* const* d_in, const int* in_sizes, int n_in,
                              void* d_out, int out_size) {
    const float* x         = (const float*)d_in[0];
    const float* w_experts = (const float*)d_in[1];
    const float* bias      = (const float*)d_in[2];
    const float* fc_w      = (const float*)d_in[3];
    const float* fc_b      = (const float*)d_in[4];
    float* out = (float*)d_out;

    const int smem_bytes = 28800 * 4;   // 115200
    cudaFuncSetAttribute(conv_kernel, cudaFuncAttributeMaxDynamicSharedMemorySize, smem_bytes);

    pool_kernel<<<1024, 256>>>(x);
    mix_kernel<<<1, 256>>>(w_experts, fc_w, fc_b);
    tag_kernel<<<1, 32>>>();
    conv_kernel<<<dim3(16, 32, 16), 256, smem_bytes>>>(x, bias, out);
}

// round 14
// speedup vs baseline: 2.9192x; 1.6354x over previous
#include <cuda_runtime.h>

// ---------------------------------------------------------------------------
// DyNet2D R13: Winograd F(4x4,3x3).
//  - phase B: vectorized two-stage transform (row then column), conflict-free
//  - bd layout [ic][q][tile][4]: STS.128 contiguous (4wf), b-loads broadcast
//  - phase C: R9's proven schedule (T=2, ic outer, q fully unrolled)
//  - 256 thr, 2 CTAs/SM, smem 115200 B
// ---------------------------------------------------------------------------

#define HW (512 * 512)

__device__ float g_partial[1024];                       // (b*16+c)*4 + quarter
__device__ __align__(16) float g_u[16 * 16 * 9 * 64];   // [b][ic][q][oc][4]

// ------------------------------ 1) pooling --------------------------------
__global__ void pool_kernel(const float* __restrict__ x) {
    const int blk = blockIdx.x;
    const int bc  = blk >> 2;
    const int q   = blk & 3;
    const float4* p = reinterpret_cast<const float4*>(x + (size_t)bc * HW + (size_t)q * 65536);
    float s = 0.0f;
    #pragma unroll 4
    for (int i = threadIdx.x; i < 16384; i += 256) {
        float4 v = p[i];
        s += (v.x + v.y) + (v.z + v.w);
    }
    #pragma unroll
    for (int o = 16; o > 0; o >>= 1) s += __shfl_down_sync(0xffffffffu, s, o);
    __shared__ float ws[8];
    if ((threadIdx.x & 31) == 0) ws[threadIdx.x >> 5] = s;
    __syncthreads();
    if (threadIdx.x == 0) {
        float t = 0.0f;
        #pragma unroll
        for (int i = 0; i < 8; i++) t += ws[i];
        g_partial[blk] = t;
    }
}

// --------------- 2) routing softmax + Winograd weight transform -----------
__global__ void mix_kernel(const float* __restrict__ w_experts,
                           const float* __restrict__ fc_w,
                           const float* __restrict__ fc_b) {
    __shared__ float pooled_s[256];
    __shared__ float r_s[16][3];
    const int tid = threadIdx.x;

    pooled_s[tid] = (g_partial[tid * 4 + 0] + g_partial[tid * 4 + 1] +
                     g_partial[tid * 4 + 2] + g_partial[tid * 4 + 3]) * (1.0f / (float)HW);
    __syncthreads();

    if (tid < 16) {
        float lg[3];
        #pragma unroll
        for (int e = 0; e < 3; e++) {
            float a = fc_b[e];
            #pragma unroll
            for (int c = 0; c < 16; c++) a += pooled_s[tid * 16 + c] * fc_w[e * 16 + c];
            lg[e] = a;
        }
        float m = fmaxf(lg[0], fmaxf(lg[1], lg[2]));
        float ex0 = expf(lg[0] - m), ex1 = expf(lg[1] - m), ex2 = expf(lg[2] - m);
        float inv = 1.0f / (ex0 + ex1 + ex2);
        r_s[tid][0] = ex0 * inv;
        r_s[tid][1] = ex1 * inv;
        r_s[tid][2] = ex2 * inv;
    }
    __syncthreads();

    for (int job = tid; job < 4096; job += 256) {
        int b  = job >> 8;
        int ic = (job >> 4) & 15;
        int oc = job & 15;

        float w[3][3];
        #pragma unroll
        for (int r = 0; r < 3; r++)
            #pragma unroll
            for (int c = 0; c < 3; c++) {
                float v = 0.0f;
                #pragma unroll
                for (int e = 0; e < 3; e++)
                    v += r_s[b][e] * w_experts[((e * 16 + oc) * 16 + ic) * 9 + r * 3 + c];
                w[r][c] = v;
            }

        float T[6][3];
        #pragma unroll
        for (int c = 0; c < 3; c++) {
            float w0 = w[0][c], w1 = w[1][c], w2 = w[2][c];
            T[0][c] = 0.25f * w0;
            T[1][c] = (-1.0f / 6.0f) * (w0 + w1 + w2);
            T[2][c] = (1.0f / 6.0f) * (-w0 + w1 - w2);
            T[3][c] = (1.0f / 24.0f) * w0 + (1.0f / 12.0f) * w1 + (1.0f / 6.0f) * w2;
            T[4][c] = (1.0f / 24.0f) * w0 - (1.0f / 12.0f) * w1 + (1.0f / 6.0f) * w2;
            T[5][c] = w2;
        }
        float u36[36];
        #pragma unroll
        for (int i = 0; i < 6; i++) {
            float t0 = T[i][0], t1 = T[i][1], t2 = T[i][2];
            u36[i * 6 + 0] = 0.25f * t0;
            u36[i * 6 + 1] = (-1.0f / 6.0f) * (t0 + t1 + t2);
            u36[i * 6 + 2] = (1.0f / 6.0f) * (-t0 + t1 - t2);
            u36[i * 6 + 3] = (1.0f / 24.0f) * t0 + (1.0f / 12.0f) * t1 + (1.0f / 6.0f) * t2;
            u36[i * 6 + 4] = (1.0f / 24.0f) * t0 - (1.0f / 12.0f) * t1 + (1.0f / 6.0f) * t2;
            u36[i * 6 + 5] = t2;
        }
        float* base = g_u + (size_t)(b * 16 + ic) * 576 + oc * 4;
        #pragma unroll
        for (int q = 0; q < 9; q++) {
            base[q * 64 + 0] = u36[q * 4 + 0];
            base[q * 64 + 1] = u36[q * 4 + 1];
            base[q * 64 + 2] = u36[q * 4 + 2];
            base[q * 64 + 3] = u36[q * 4 + 3];
        }
    }
}

// ------- no-op: shifts ncu's -s 5 capture slot onto conv_kernel -----------
__global__ void tag_kernel() {}

// ------------------------- 3) Winograd conv -------------------------------
__device__ __forceinline__ void btrans(float v0, float v1, float v2, float v3,
                                       float v4, float v5,
                                       float& o0, float& o1, float& o2,
                                       float& o3, float& o4, float& o5) {
    float a = v1 + v2;
    float b = v3 + v4;
    float c = v1 - v2;
    float e = v4 - v3;
    float f = v3 - v1;
    float g = v4 - v2;
    o0 = fmaf(4.0f, v0, fmaf(-5.0f, v2, v4));
    o1 = fmaf(-4.0f, a, b);
    o2 = fmaf(4.0f, c, e);
    o3 = fmaf(2.0f, f, g);
    o4 = fmaf(-2.0f, f, g);
    o5 = fmaf(4.0f, v1, fmaf(-5.0f, v3, v5));
}

__device__ __forceinline__ void atrans(float v0, float v1, float v2, float v3,
                                       float v4, float v5,
                                       float& o0, float& o1, float& o2, float& o3) {
    float s1 = v1 + v2;
    float s2 = v1 - v2;
    float s3 = v3 + v4;
    float s4 = v3 - v4;
    o0 = v0 + s1 + s3;
    o1 = fmaf(2.0f, s4, s2);
    o2 = fmaf(4.0f, s3, s1);
    o3 = fmaf(8.0f, s4, s2) + v5;
}

// SMEM (floats):
//   bd_s  : [16 ic][9 q][32 tile][4] -> 18432  (offset 0)
//   union : 10368                      (offset 18432)
//       phases A/B: in_s [16 ic][18 rows][36 stride] (cols 0..33 used)
//       phase  C  : w_s  [16 ic][9 q][16 oc][4] = 9216
// total 28800 floats = 115200 bytes -> 2 CTAs/SM
__global__ void __launch_bounds__(256, 2)
conv_kernel(const float* __restrict__ x, const float* __restrict__ bias,
            float* __restrict__ out) {
    extern __shared__ float smem[];
    float* bd_s = smem;
    float* un_s = smem + 18432;      // in_s during A/B, w_s during C

    const int tid = threadIdx.x;
    const int b   = blockIdx.z;
    const int x0  = blockIdx.x * 32;
    const int y0  = blockIdx.y * 16;

    const int oc  = tid & 15;
    const int grp = tid >> 4;        // 0..15 -> tiles 2*grp, 2*grp+1

    const float bv = bias[oc];
    const float* xb = x + (size_t)b * 16 * HW;

    // ---- phase A: input tile 16ic x 18 x 34 (reflect halo), stride 36 ----
    for (int i = tid; i < 9792; i += 256) {
        int c   = i / 612;                   // 18*34
        int rem = i - c * 612;
        int row = rem / 34;
        int col = rem - row * 34;
        int gy = y0 + row - 1; gy = gy < 0 ? -gy : (gy > 511 ? 1022 - gy : gy);
        int gx = x0 + col - 1; gx = gx < 0 ? -gx : (gx > 511 ? 1022 - gx : gx);
        un_s[c * 648 + row * 36 + col] = xb[(c << 18) + (gy << 9) + gx];
    }
    __syncthreads();

    // ---- phase B: vectorized two-stage input transform, 2 jobs/thread ----
    // Stage 1: per row r, vector-load d-row and row-transform -> rowt (D*B).
    // Stage 2: per column j, column-transform -> bd (B^T*D*B), static idx.
    #pragma unroll 1
    for (int s = 0; s < 2; s++) {
        const int job  = tid + s * 256;
        const int b_ic = job >> 5;
        const int b_t  = job & 31;
        const int b_tx = b_t & 7;
        const int b_ty = b_t >> 3;
        const float* p = un_s + b_ic * 648 + (4 * b_ty) * 36 + 4 * b_tx;

        float rowt[6][6];
        #pragma unroll
        for (int r = 0; r < 6; r++) {
            float4 a  = *reinterpret_cast<const float4*>(p + r * 36);
            float2 b2 = *reinterpret_cast<const float2*>(p + r * 36 + 4);
            btrans(a.x, a.y, a.z, a.w, b2.x, b2.y,
                   rowt[r][0], rowt[r][1], rowt[r][2],
                   rowt[r][3], rowt[r][4], rowt[r][5]);
        }
        float bd[36];
        #pragma unroll
        for (int j = 0; j < 6; j++)
            btrans(rowt[0][j], rowt[1][j], rowt[2][j],
                   rowt[3][j], rowt[4][j], rowt[5][j],
                   bd[0 + j], bd[6 + j], bd[12 + j],
                   bd[18 + j], bd[24 + j], bd[30 + j]);

        // [ic][q][tile][4]: warp writes 32 consecutive tiles -> 512B contiguous
        float* dst = bd_s + b_ic * 1152 + b_t * 4;
        #pragma unroll
        for (int q = 0; q < 9; q++)
            *reinterpret_cast<float4*>(dst + q * 128) =
                make_float4(bd[q * 4 + 0], bd[q * 4 + 1], bd[q * 4 + 2], bd[q * 4 + 3]);
    }
    __syncthreads();

    // ---- load transformed weights into union (in_s dead now) ----
    {
        const float4* src = reinterpret_cast<const float4*>(g_u + (size_t)b * 9216);
        float4* dst = reinterpret_cast<float4*>(un_s);
        #pragma unroll
        for (int k = 0; k < 9; k++) {
            int i = tid + k * 256;
            if (i < 2304) dst[i] = src[i];
        }
    }
    __syncthreads();

    // ---- phase C: R9 schedule (ic outer, q fully unrolled), new bd addrs --
    float m0[36], m1[36];
    #pragma unroll
    for (int j = 0; j < 36; j++) { m0[j] = 0.0f; m1[j] = 0.0f; }
    {
        const float* wq  = un_s + oc * 4;       // + ic*576 + q*64
        const float* bdq = bd_s + grp * 8;      // + ic*1152 + q*128 (b1 = +4)
        #pragma unroll 1
        for (int ic = 0; ic < 16; ic++) {
            #pragma unroll
            for (int q = 0; q < 9; q++) {
                float4 u  = *reinterpret_cast<const float4*>(wq  + q * 64);
                float4 b0 = *reinterpret_cast<const float4*>(bdq + q * 128);
                float4 b1 = *reinterpret_cast<const float4*>(bdq + q * 128 + 4);
                m0[q*4+0] = fmaf(b0.x, u.x, m0[q*4+0]);
                m0[q*4+1] = fmaf(b0.y, u.y, m0[q*4+1]);
                m0[q*4+2] = fmaf(b0.z, u.z, m0[q*4+2]);
                m0[q*4+3] = fmaf(b0.w, u.w, m0[q*4+3]);
                m1[q*4+0] = fmaf(b1.x, u.x, m1[q*4+0]);
                m1[q*4+1] = fmaf(b1.y, u.y, m1[q*4+1]);
                m1[q*4+2] = fmaf(b1.z, u.z, m1[q*4+2]);
                m1[q*4+3] = fmaf(b1.w, u.w, m1[q*4+3]);
            }
            wq  += 576;
            bdq += 1152;
        }
    }

    // ---- phase D: A^T m A + bias for both tiles ----
    #pragma unroll
    for (int t2 = 0; t2 < 2; t2++) {
        const float* m = t2 ? m1 : m0;
        const int tile = grp * 2 + t2;
        const int tx = tile & 7;
        const int ty = tile >> 3;

        float t[4][6];
        #pragma unroll
        for (int j = 0; j < 6; j++)
            atrans(m[0 * 6 + j], m[1 * 6 + j], m[2 * 6 + j],
                   m[3 * 6 + j], m[4 * 6 + j], m[5 * 6 + j],
                   t[0][j], t[1][j], t[2][j], t[3][j]);

        float* op = out + ((size_t)(b * 16 + oc) << 18) +
                    ((size_t)(y0 + 4 * ty) << 9) + (x0 + 4 * tx);
        #pragma unroll
        for (int r = 0; r < 4; r++) {
            float o0, o1, o2, o3;
            atrans(t[r][0], t[r][1], t[r][2], t[r][3], t[r][4], t[r][5],
                   o0, o1, o2, o3);
            *reinterpret_cast<float4*>(op + ((size_t)r << 9)) =
                make_float4(o0 + bv, o1 + bv, o2 + bv, o3 + bv);
        }
    }
}

// ---------------------------------------------------------------------------
extern "C" void kernel_launch(void* const* d_in, const int* in_sizes, int n_in,
                              void* d_out, int out_size) {
    const float* x         = (const float*)d_in[0];
    const float* w_experts = (const float*)d_in[1];
    const float* bias      = (const float*)d_in[2];
    const float* fc_w      = (const float*)d_in[3];
    const float* fc_b      = (const float*)d_in[4];
    float* out = (float*)d_out;

    const int smem_bytes = 28800 * 4;   // 115200
    cudaFuncSetAttribute(conv_kernel, cudaFuncAttributeMaxDynamicSharedMemorySize, smem_bytes);

    pool_kernel<<<1024, 256>>>(x);
    mix_kernel<<<1, 256>>>(w_experts, fc_w, fc_b);
    tag_kernel<<<1, 32>>>();
    conv_kernel<<<dim3(16, 32, 16), 256, smem_bytes>>>(x, bias, out);
}